// round 1
// baseline (speedup 1.0000x reference)
#include <cuda_runtime.h>
#include <math.h>
#include <stdint.h>
#include <stddef.h>

// Problem dims (fixed by the dataset)
constexpr int N_IMG = 256;   // Bi
constexpr int N_CAP = 256;   // Bc
constexpr int T_WORDS = 64;  // T
constexpr int DIM = 1024;    // D
constexpr int DRED = 256;    // Dr
constexpr int LREG = 36;     // L

// -------------------- scratch (device globals; no allocs allowed) ------------
__device__ float  g_capfull[N_CAP * DIM];     // masked mean of cap_embed
__device__ float  g_capv   [N_CAP * DIM];     // l2-normalized cap_full
__device__ float  g_capr   [N_CAP * DRED];    // cap_repr
__device__ float2 g_w      [N_CAP];           // (w0, w2) softmax weights
__device__ float  g_X      [3 * N_IMG * DIM]; // rows: [S ; row35 ; row0]
__device__ float  g_Y      [3 * N_IMG * DIM]; // rows: [P ; Q ; R]  (post conv + scale/bias)
__device__ float  g_Z      [3 * N_IMG * N_CAP]; // [P;Q;R] @ cap_v^T
__device__ float  g_gram   [N_IMG * 6];       // PP QQ RR PQ PR QR

// -------------------- helpers ------------------------------------------------
__device__ __forceinline__ float block_reduce_sum(float v, float* smem) {
    __syncthreads();  // protect smem reuse across sequential calls
    int lane = threadIdx.x & 31, warp = threadIdx.x >> 5;
    #pragma unroll
    for (int o = 16; o; o >>= 1) v += __shfl_down_sync(0xffffffffu, v, o);
    if (lane == 0) smem[warp] = v;
    __syncthreads();
    if (warp == 0) {
        v = (lane < (int)(blockDim.x >> 5)) ? smem[lane] : 0.f;
        #pragma unroll
        for (int o = 4; o; o >>= 1) v += __shfl_down_sync(0xffffffffu, v, o);
        if (lane == 0) smem[0] = v;
    }
    __syncthreads();
    return smem[0];
}

// -------------------- k1: caption masked mean + l2 norm ---------------------
__global__ __launch_bounds__(256) void cap_reduce_kernel(
    const float* __restrict__ cap, const int* __restrict__ lens)
{
    __shared__ float smem[32];
    const int b = blockIdx.x;
    const int t4 = threadIdx.x;  // float4 index over D (1024/4 = 256)
    const float4* c4 = reinterpret_cast<const float4*>(cap) + (size_t)b * (T_WORDS * DIM / 4);
    const int len = lens[b];
    float4 a = make_float4(0.f, 0.f, 0.f, 0.f);
    for (int t = 0; t < len; t++) {
        float4 v = c4[t * (DIM / 4) + t4];
        a.x += v.x; a.y += v.y; a.z += v.z; a.w += v.w;
    }
    const float inv = 1.f / (float)len;
    a.x *= inv; a.y *= inv; a.z *= inv; a.w *= inv;
    reinterpret_cast<float4*>(g_capfull)[b * (DIM / 4) + t4] = a;
    float ss = a.x * a.x + a.y * a.y + a.z * a.z + a.w * a.w;
    ss = block_reduce_sum(ss, smem);
    const float invn = 1.f / (sqrtf(ss) + 1e-8f);
    a.x *= invn; a.y *= invn; a.z *= invn; a.w *= invn;
    reinterpret_cast<float4*>(g_capv)[b * (DIM / 4) + t4] = a;
}

// -------------------- k4: image region sum + edge rows ----------------------
__global__ __launch_bounds__(256) void img_reduce_kernel(const float* __restrict__ img)
{
    const int i = blockIdx.x;
    const int t4 = threadIdx.x;
    const float4* p = reinterpret_cast<const float4*>(img) + (size_t)i * (LREG * DIM / 4);
    float4 s = make_float4(0.f, 0.f, 0.f, 0.f);
    float4 r0 = make_float4(0.f, 0.f, 0.f, 0.f);
    float4 rl = make_float4(0.f, 0.f, 0.f, 0.f);
    for (int l = 0; l < LREG; l++) {
        float4 v = p[l * (DIM / 4) + t4];
        if (l == 0) r0 = v;
        rl = v;  // keeps l = LREG-1 value
        s.x += v.x; s.y += v.y; s.z += v.z; s.w += v.w;
    }
    float4* X4 = reinterpret_cast<float4*>(g_X);
    X4[(0 * N_IMG + i) * (DIM / 4) + t4] = s;   // S
    X4[(1 * N_IMG + i) * (DIM / 4) + t4] = rl;  // row 35
    X4[(2 * N_IMG + i) * (DIM / 4) + t4] = r0;  // row 0
}

// -------------------- generic NT GEMM: C[m,n] = sum_k A[m,k]*B[n,k] ---------
// A: (M,K) row-major, B: (N,K) row-major (both K-contiguous).
// Epilogue: C = acc*scale (+ bias[n] for rows m < bias_rows).
template <int BM, int BN, int BK, int TM, int TN>
__global__ __launch_bounds__(256) void gemm_nt(
    const float* __restrict__ A, const float* __restrict__ B, float* __restrict__ C,
    int M, int N, int K, float scale, const float* __restrict__ bias, int bias_rows)
{
    __shared__ float As[BK][BM + 4];
    __shared__ float Bs[BK][BN + 4];
    const int tid = threadIdx.x;
    const int bm0 = blockIdx.y * BM;
    const int bn0 = blockIdx.x * BN;
    const int tx = tid % (BN / TN);
    const int ty = tid / (BN / TN);

    float acc[TM][TN];
    #pragma unroll
    for (int i = 0; i < TM; i++)
        #pragma unroll
        for (int j = 0; j < TN; j++) acc[i][j] = 0.f;

    for (int k0 = 0; k0 < K; k0 += BK) {
        #pragma unroll
        for (int idx = tid; idx < BM * (BK / 4); idx += 256) {
            const int row = idx / (BK / 4);
            const int kc  = idx % (BK / 4);
            float4 v = *reinterpret_cast<const float4*>(A + (size_t)(bm0 + row) * K + k0 + kc * 4);
            As[kc * 4 + 0][row] = v.x; As[kc * 4 + 1][row] = v.y;
            As[kc * 4 + 2][row] = v.z; As[kc * 4 + 3][row] = v.w;
        }
        #pragma unroll
        for (int idx = tid; idx < BN * (BK / 4); idx += 256) {
            const int row = idx / (BK / 4);
            const int kc  = idx % (BK / 4);
            float4 v = *reinterpret_cast<const float4*>(B + (size_t)(bn0 + row) * K + k0 + kc * 4);
            Bs[kc * 4 + 0][row] = v.x; Bs[kc * 4 + 1][row] = v.y;
            Bs[kc * 4 + 2][row] = v.z; Bs[kc * 4 + 3][row] = v.w;
        }
        __syncthreads();
        #pragma unroll
        for (int kk = 0; kk < BK; kk++) {
            float a[TM], b[TN];
            if constexpr (TM == 4) {
                float4 v = *reinterpret_cast<const float4*>(&As[kk][ty * TM]);
                a[0] = v.x; a[1] = v.y; a[2] = v.z; a[3] = v.w;
            } else {
                float2 v = *reinterpret_cast<const float2*>(&As[kk][ty * TM]);
                a[0] = v.x; a[1] = v.y;
            }
            if constexpr (TN == 4) {
                float4 v = *reinterpret_cast<const float4*>(&Bs[kk][tx * TN]);
                b[0] = v.x; b[1] = v.y; b[2] = v.z; b[3] = v.w;
            } else {
                float2 v = *reinterpret_cast<const float2*>(&Bs[kk][tx * TN]);
                b[0] = v.x; b[1] = v.y;
            }
            #pragma unroll
            for (int i = 0; i < TM; i++)
                #pragma unroll
                for (int j = 0; j < TN; j++)
                    acc[i][j] = fmaf(a[i], b[j], acc[i][j]);
        }
        __syncthreads();
    }

    #pragma unroll
    for (int i = 0; i < TM; i++) {
        const int m = bm0 + ty * TM + i;
        #pragma unroll
        for (int j = 0; j < TN; j++) {
            const int n = bn0 + tx * TN + j;
            float v = acc[i][j] * scale;
            if (bias != nullptr && m < bias_rows) v += bias[n];
            C[(size_t)m * N + n] = v;
        }
    }
}

// -------------------- k3: logits + 3-way softmax -> (w0, w2) ----------------
__global__ __launch_bounds__(256) void softmax_w_kernel(
    const float* __restrict__ pw, const float* __restrict__ pb)
{
    const int warp = threadIdx.x >> 5, lane = threadIdx.x & 31;
    const int b = blockIdx.x * 8 + warp;
    float s0 = 0.f, s1 = 0.f, s2 = 0.f;
    for (int e = lane; e < DRED; e += 32) {
        const float r = g_capr[b * DRED + e];
        s0 = fmaf(r, pw[0 * DRED + e], s0);
        s1 = fmaf(r, pw[1 * DRED + e], s1);
        s2 = fmaf(r, pw[2 * DRED + e], s2);
    }
    #pragma unroll
    for (int o = 16; o; o >>= 1) {
        s0 += __shfl_down_sync(0xffffffffu, s0, o);
        s1 += __shfl_down_sync(0xffffffffu, s1, o);
        s2 += __shfl_down_sync(0xffffffffu, s2, o);
    }
    if (lane == 0) {
        s0 += pb[0]; s1 += pb[1]; s2 += pb[2];
        const float m = fmaxf(s0, fmaxf(s1, s2));
        const float e0 = expf(s0 - m), e1 = expf(s1 - m), e2 = expf(s2 - m);
        const float inv = 1.f / (e0 + e1 + e2);
        g_w[b] = make_float2(e0 * inv, e2 * inv);
    }
}

// -------------------- k6: per-image 3x3 Gram of {P,Q,R} ---------------------
__global__ __launch_bounds__(256) void gram_kernel()
{
    __shared__ float smem[32];
    const int i = blockIdx.x;
    float pp = 0, qq = 0, rr = 0, pq = 0, pr = 0, qr = 0;
    for (int d = threadIdx.x; d < DIM; d += 256) {
        const float p = g_Y[(size_t)(0 * N_IMG + i) * DIM + d];
        const float q = g_Y[(size_t)(1 * N_IMG + i) * DIM + d];
        const float r = g_Y[(size_t)(2 * N_IMG + i) * DIM + d];
        pp = fmaf(p, p, pp); qq = fmaf(q, q, qq); rr = fmaf(r, r, rr);
        pq = fmaf(p, q, pq); pr = fmaf(p, r, pr); qr = fmaf(q, r, qr);
    }
    pp = block_reduce_sum(pp, smem);
    qq = block_reduce_sum(qq, smem);
    rr = block_reduce_sum(rr, smem);
    pq = block_reduce_sum(pq, smem);
    pr = block_reduce_sum(pr, smem);
    qr = block_reduce_sum(qr, smem);
    if (threadIdx.x == 0) {
        float* g = &g_gram[i * 6];
        g[0] = pp; g[1] = qq; g[2] = rr; g[3] = pq; g[4] = pr; g[5] = qr;
    }
}

// -------------------- k8: combine everything into sims ----------------------
__global__ __launch_bounds__(256) void final_kernel(float* __restrict__ out)
{
    const int i = blockIdx.x, b = threadIdx.x;
    const float2 w = g_w[b];
    const float zp = g_Z[(size_t)(0 * N_IMG + i) * N_CAP + b];
    const float zq = g_Z[(size_t)(1 * N_IMG + i) * N_CAP + b];
    const float zr = g_Z[(size_t)(2 * N_IMG + i) * N_CAP + b];
    const float* g = &g_gram[i * 6];
    const float numer = zp - w.x * zq - w.y * zr;
    const float den2 = g[0] + w.x * w.x * g[1] + w.y * w.y * g[2]
                     - 2.f * w.x * g[3] - 2.f * w.y * g[4] + 2.f * w.x * w.y * g[5];
    out[(size_t)i * N_CAP + b] = numer / (sqrtf(fmaxf(den2, 0.f)) + 1e-8f);
}

// -------------------- launch -------------------------------------------------
extern "C" void kernel_launch(void* const* d_in, const int* in_sizes, int n_in,
                              void* d_out, int out_size)
{
    const float* img    = (const float*)d_in[0];
    const float* cap    = (const float*)d_in[1];
    const int*   lens   = (const int*)  d_in[2];
    const float* red_w  = (const float*)d_in[3];
    const float* red_b  = (const float*)d_in[4];
    const float* proj_w = (const float*)d_in[5];
    const float* proj_b = (const float*)d_in[6];
    const float* conv_w = (const float*)d_in[7];
    const float* conv_b = (const float*)d_in[8];
    float* out = (float*)d_out;

    float *pCF, *pCV, *pCR, *pX, *pY, *pZ;
    cudaGetSymbolAddress((void**)&pCF, g_capfull);
    cudaGetSymbolAddress((void**)&pCV, g_capv);
    cudaGetSymbolAddress((void**)&pCR, g_capr);
    cudaGetSymbolAddress((void**)&pX,  g_X);
    cudaGetSymbolAddress((void**)&pY,  g_Y);
    cudaGetSymbolAddress((void**)&pZ,  g_Z);

    // Caption branch
    cap_reduce_kernel<<<N_CAP, 256>>>(cap, lens);
    gemm_nt<32, 32, 32, 2, 2><<<dim3(DRED / 32, N_CAP / 32), 256>>>(
        pCF, red_w, pCR, N_CAP, DRED, DIM, 1.f, red_b, N_CAP);
    softmax_w_kernel<<<N_CAP / 8, 256>>>(proj_w, proj_b);

    // Image branch
    img_reduce_kernel<<<N_IMG, 256>>>(img);
    gemm_nt<64, 64, 32, 4, 4><<<dim3(DIM / 64, (3 * N_IMG) / 64), 256>>>(
        pX, conv_w, pY, 3 * N_IMG, DIM, DIM, 1.f / (float)LREG, conv_b, N_IMG);
    gram_kernel<<<N_IMG, 256>>>();

    // Cross terms + combine
    gemm_nt<32, 32, 32, 2, 2><<<dim3(N_CAP / 32, (3 * N_IMG) / 32), 256>>>(
        pY, pCV, pZ, 3 * N_IMG, N_CAP, DIM, 1.f, nullptr, 0);
    final_kernel<<<N_IMG, 256>>>(out);
}

// round 2
// speedup vs baseline: 1.5750x; 1.5750x over previous
#include <cuda_runtime.h>
#include <cuda_bf16.h>
#include <math.h>
#include <stdint.h>
#include <stddef.h>

// Problem dims (fixed by the dataset)
constexpr int N_IMG = 256;   // Bi
constexpr int N_CAP = 256;   // Bc
constexpr int T_WORDS = 64;  // T
constexpr int DIM = 1024;    // D
constexpr int DRED = 256;    // Dr
constexpr int LREG = 36;     // L
constexpr int MROWS = 3 * N_IMG;  // 768 rows: [S ; row35 ; row0]
constexpr int NSPLIT = 4;         // split-K for Z gemm

// -------------------- scratch (device globals; no allocs allowed) ------------
__device__ float          g_capfull[N_CAP * DIM];
__device__ __nv_bfloat16  g_cv_hi [N_CAP * DIM];
__device__ __nv_bfloat16  g_cv_lo [N_CAP * DIM];
__device__ float          g_capr  [N_CAP * DRED];
__device__ float2         g_w     [N_CAP];
__device__ __nv_bfloat16  g_X_hi  [MROWS * DIM];
__device__ __nv_bfloat16  g_X_lo  [MROWS * DIM];
__device__ __nv_bfloat16  g_W_hi  [DIM * DIM];
__device__ __nv_bfloat16  g_W_lo  [DIM * DIM];
__device__ float          g_Yf    [MROWS * DIM];
__device__ __nv_bfloat16  g_Y_hi  [MROWS * DIM];
__device__ __nv_bfloat16  g_Y_lo  [MROWS * DIM];
__device__ float          g_Zpart [NSPLIT * MROWS * N_CAP];
__device__ float          g_gram  [N_IMG * 6];

// -------------------- helpers ------------------------------------------------
__device__ __forceinline__ float block_reduce_sum(float v, float* smem) {
    __syncthreads();
    int lane = threadIdx.x & 31, warp = threadIdx.x >> 5;
    #pragma unroll
    for (int o = 16; o; o >>= 1) v += __shfl_down_sync(0xffffffffu, v, o);
    if (lane == 0) smem[warp] = v;
    __syncthreads();
    if (warp == 0) {
        v = (lane < (int)(blockDim.x >> 5)) ? smem[lane] : 0.f;
        #pragma unroll
        for (int o = 4; o; o >>= 1) v += __shfl_down_sync(0xffffffffu, v, o);
        if (lane == 0) smem[0] = v;
    }
    __syncthreads();
    return smem[0];
}

// split x -> hi + lo (bf16 pair); hi*hi+hi*lo+lo*hi recovers ~2^-16 accuracy
__device__ __forceinline__ void bf_split(float x, __nv_bfloat16& h, __nv_bfloat16& l) {
    h = __float2bfloat16(x);
    l = __float2bfloat16(x - __bfloat162float(h));
}

// store float4 as 4 hi-bf16 + 4 lo-bf16 (two 8B stores)
__device__ __forceinline__ void split_store4(__nv_bfloat16* hi, __nv_bfloat16* lo,
                                             size_t idx, float4 v) {
    union { __nv_bfloat16 b[4]; uint2 u; } H, L;
    bf_split(v.x, H.b[0], L.b[0]); bf_split(v.y, H.b[1], L.b[1]);
    bf_split(v.z, H.b[2], L.b[2]); bf_split(v.w, H.b[3], L.b[3]);
    *reinterpret_cast<uint2*>(hi + idx) = H.u;
    *reinterpret_cast<uint2*>(lo + idx) = L.u;
}

// -------------------- k1: caption masked mean + l2 norm ---------------------
__global__ __launch_bounds__(256) void cap_reduce_kernel(
    const float* __restrict__ cap, const int* __restrict__ lens)
{
    __shared__ float smem[32];
    const int b = blockIdx.x;
    const int t4 = threadIdx.x;  // 1024/4 = 256 float4 lanes
    const float4* c4 = reinterpret_cast<const float4*>(cap) + (size_t)b * (T_WORDS * DIM / 4);
    const int len = lens[b];
    float4 a = make_float4(0.f, 0.f, 0.f, 0.f);
    int t = 0;
    for (; t + 4 <= len; t += 4) {
        float4 v0 = c4[(t + 0) * (DIM / 4) + t4];
        float4 v1 = c4[(t + 1) * (DIM / 4) + t4];
        float4 v2 = c4[(t + 2) * (DIM / 4) + t4];
        float4 v3 = c4[(t + 3) * (DIM / 4) + t4];
        a.x += v0.x + v1.x + v2.x + v3.x;
        a.y += v0.y + v1.y + v2.y + v3.y;
        a.z += v0.z + v1.z + v2.z + v3.z;
        a.w += v0.w + v1.w + v2.w + v3.w;
    }
    for (; t < len; t++) {
        float4 v = c4[t * (DIM / 4) + t4];
        a.x += v.x; a.y += v.y; a.z += v.z; a.w += v.w;
    }
    const float inv = 1.f / (float)len;
    a.x *= inv; a.y *= inv; a.z *= inv; a.w *= inv;
    reinterpret_cast<float4*>(g_capfull)[b * (DIM / 4) + t4] = a;
    float ss = a.x * a.x + a.y * a.y + a.z * a.z + a.w * a.w;
    ss = block_reduce_sum(ss, smem);
    const float invn = 1.f / (sqrtf(ss) + 1e-8f);
    a.x *= invn; a.y *= invn; a.z *= invn; a.w *= invn;
    split_store4(g_cv_hi, g_cv_lo, ((size_t)b * DIM) + (size_t)t4 * 4, a);
}

// -------------------- k4: image region sum + edge rows (bf16 split out) -----
__global__ __launch_bounds__(256) void img_reduce_kernel(const float* __restrict__ img)
{
    const int i = blockIdx.x;
    const int t4 = threadIdx.x;
    const float4* p = reinterpret_cast<const float4*>(img) + (size_t)i * (LREG * DIM / 4);
    float4 s = make_float4(0.f, 0.f, 0.f, 0.f);
    float4 r0 = make_float4(0.f, 0.f, 0.f, 0.f);
    float4 rl = make_float4(0.f, 0.f, 0.f, 0.f);
    #pragma unroll
    for (int l = 0; l < LREG; l++) {
        float4 v = p[l * (DIM / 4) + t4];
        if (l == 0) r0 = v;
        if (l == LREG - 1) rl = v;
        s.x += v.x; s.y += v.y; s.z += v.z; s.w += v.w;
    }
    const size_t d0 = (size_t)t4 * 4;
    split_store4(g_X_hi, g_X_lo, (size_t)(0 * N_IMG + i) * DIM + d0, s);
    split_store4(g_X_hi, g_X_lo, (size_t)(1 * N_IMG + i) * DIM + d0, rl);
    split_store4(g_X_hi, g_X_lo, (size_t)(2 * N_IMG + i) * DIM + d0, r0);
}

// -------------------- k5: split conv_w into bf16 hi/lo ----------------------
__global__ __launch_bounds__(256) void wsplit_kernel(const float* __restrict__ w)
{
    const size_t idx4 = (size_t)blockIdx.x * 256 + threadIdx.x;  // float4 index
    float4 v = reinterpret_cast<const float4*>(w)[idx4];
    split_store4(g_W_hi, g_W_lo, idx4 * 4, v);
}

// -------------------- SIMT NT GEMM (kept for small red gemm) ----------------
template <int BM, int BN, int BK, int TM, int TN>
__global__ __launch_bounds__(256) void gemm_nt(
    const float* __restrict__ A, const float* __restrict__ B, float* __restrict__ C,
    int M, int N, int K, float scale, const float* __restrict__ bias)
{
    __shared__ float As[BK][BM + 4];
    __shared__ float Bs[BK][BN + 4];
    const int tid = threadIdx.x;
    const int bm0 = blockIdx.y * BM;
    const int bn0 = blockIdx.x * BN;
    const int tx = tid % (BN / TN);
    const int ty = tid / (BN / TN);

    float acc[TM][TN];
    #pragma unroll
    for (int i = 0; i < TM; i++)
        #pragma unroll
        for (int j = 0; j < TN; j++) acc[i][j] = 0.f;

    for (int k0 = 0; k0 < K; k0 += BK) {
        #pragma unroll
        for (int idx = tid; idx < BM * (BK / 4); idx += 256) {
            const int row = idx / (BK / 4);
            const int kc  = idx % (BK / 4);
            float4 v = *reinterpret_cast<const float4*>(A + (size_t)(bm0 + row) * K + k0 + kc * 4);
            As[kc * 4 + 0][row] = v.x; As[kc * 4 + 1][row] = v.y;
            As[kc * 4 + 2][row] = v.z; As[kc * 4 + 3][row] = v.w;
        }
        #pragma unroll
        for (int idx = tid; idx < BN * (BK / 4); idx += 256) {
            const int row = idx / (BK / 4);
            const int kc  = idx % (BK / 4);
            float4 v = *reinterpret_cast<const float4*>(B + (size_t)(bn0 + row) * K + k0 + kc * 4);
            Bs[kc * 4 + 0][row] = v.x; Bs[kc * 4 + 1][row] = v.y;
            Bs[kc * 4 + 2][row] = v.z; Bs[kc * 4 + 3][row] = v.w;
        }
        __syncthreads();
        #pragma unroll
        for (int kk = 0; kk < BK; kk++) {
            float a[TM], b[TN];
            float2 va = *reinterpret_cast<const float2*>(&As[kk][ty * TM]);
            a[0] = va.x; a[1] = va.y;
            float2 vb = *reinterpret_cast<const float2*>(&Bs[kk][tx * TN]);
            b[0] = vb.x; b[1] = vb.y;
            #pragma unroll
            for (int i = 0; i < TM; i++)
                #pragma unroll
                for (int j = 0; j < TN; j++)
                    acc[i][j] = fmaf(a[i], b[j], acc[i][j]);
        }
        __syncthreads();
    }

    #pragma unroll
    for (int i = 0; i < TM; i++) {
        const int m = bm0 + ty * TM + i;
        #pragma unroll
        for (int j = 0; j < TN; j++) {
            const int n = bn0 + tx * TN + j;
            float v = acc[i][j] * scale;
            if (bias != nullptr) v += bias[n];
            C[(size_t)m * N + n] = v;
        }
    }
}

// -------------------- tensor-core NT GEMM, split-bf16 (3-term) --------------
// C[m,n] = sum_k A[m,k]*B[n,k], A/B given as hi/lo bf16 arrays (K-contig).
// MODE 0: C = acc*scale (+bias[n] for m<bias_rows); writes Cf32 + Chi/Clo.
// MODE 1: partial (split-K over blockIdx.z): Cpart[z][m][n] = acc.
#define MMA_BF16(c, a, b)                                                      \
    asm volatile("mma.sync.aligned.m16n8k16.row.col.f32.bf16.bf16.f32 "        \
                 "{%0,%1,%2,%3}, {%4,%5,%6,%7}, {%8,%9}, {%0,%1,%2,%3};"       \
                 : "+f"((c)[0]), "+f"((c)[1]), "+f"((c)[2]), "+f"((c)[3])      \
                 : "r"((a)[0]), "r"((a)[1]), "r"((a)[2]), "r"((a)[3]),         \
                   "r"((b)[0]), "r"((b)[1]))

constexpr int GBM = 64, GBN = 64, GBK = 32, GBKP = 40;  // smem pitch 40 bf16

__device__ __forceinline__ void tile_gload(uint4* pf,
    const __nv_bfloat16* a_hi, const __nv_bfloat16* a_lo,
    const __nv_bfloat16* b_hi, const __nv_bfloat16* b_lo,
    int K, int k0, int tid)
{
    const __nv_bfloat16* src[4] = {a_hi, a_lo, b_hi, b_lo};
    #pragma unroll
    for (int a = 0; a < 4; a++)
        #pragma unroll
        for (int it = 0; it < 2; it++) {
            const int idx = tid + it * 128;
            const int row = idx >> 2, c4 = idx & 3;
            pf[a * 2 + it] = *reinterpret_cast<const uint4*>(
                src[a] + (size_t)row * K + k0 + c4 * 8);
        }
}

__device__ __forceinline__ void tile_sstore(const uint4* pf,
    __nv_bfloat16 (*sm)[GBM][GBKP], int tid)
{
    #pragma unroll
    for (int a = 0; a < 4; a++)
        #pragma unroll
        for (int it = 0; it < 2; it++) {
            const int idx = tid + it * 128;
            const int row = idx >> 2, c4 = idx & 3;
            uint2* d = reinterpret_cast<uint2*>(&sm[a][row][c4 * 8]);
            const uint4 v = pf[a * 2 + it];
            d[0] = make_uint2(v.x, v.y);
            d[1] = make_uint2(v.z, v.w);
        }
}

template <int MODE>
__global__ __launch_bounds__(128) void mma_gemm_nt(
    const __nv_bfloat16* __restrict__ Ahi, const __nv_bfloat16* __restrict__ Alo,
    const __nv_bfloat16* __restrict__ Bhi, const __nv_bfloat16* __restrict__ Blo,
    float* __restrict__ Cf, __nv_bfloat16* __restrict__ Chi, __nv_bfloat16* __restrict__ Clo,
    int M, int N, int K, int KLEN, float scale,
    const float* __restrict__ bias, int bias_rows)
{
    __shared__ __align__(16) __nv_bfloat16 sm[4][GBM][GBKP];  // Ahi, Alo, Bhi, Blo

    const int tid  = threadIdx.x;
    const int lane = tid & 31;
    const int warp = tid >> 5;
    const int wm = warp >> 1, wn = warp & 1;       // 2x2 warps, 32x32 each
    const int bm0 = blockIdx.y * GBM;
    const int bn0 = blockIdx.x * GBN;
    const int kbase = blockIdx.z * KLEN;
    const int KT = KLEN / GBK;

    const __nv_bfloat16* pAh = Ahi + (size_t)bm0 * K;
    const __nv_bfloat16* pAl = Alo + (size_t)bm0 * K;
    const __nv_bfloat16* pBh = Bhi + (size_t)bn0 * K;
    const __nv_bfloat16* pBl = Blo + (size_t)bn0 * K;

    float acc[2][4][4];
    #pragma unroll
    for (int mt = 0; mt < 2; mt++)
        #pragma unroll
        for (int nt = 0; nt < 4; nt++)
            #pragma unroll
            for (int r = 0; r < 4; r++) acc[mt][nt][r] = 0.f;

    uint4 pf[8];
    tile_gload(pf, pAh, pAl, pBh, pBl, K, kbase, tid);
    tile_sstore(pf, sm, tid);
    __syncthreads();

    for (int kt = 0; kt < KT; kt++) {
        if (kt + 1 < KT)
            tile_gload(pf, pAh, pAl, pBh, pBl, K, kbase + (kt + 1) * GBK, tid);

        #pragma unroll
        for (int s = 0; s < 2; s++) {
            const int kk = s * 16 + (lane & 3) * 2;
            unsigned aH[2][4], aL[2][4], bH[4][2], bL[4][2];
            #pragma unroll
            for (int mt = 0; mt < 2; mt++) {
                const int r = wm * 32 + mt * 16 + (lane >> 2);
                aH[mt][0] = *reinterpret_cast<const unsigned*>(&sm[0][r    ][kk]);
                aH[mt][1] = *reinterpret_cast<const unsigned*>(&sm[0][r + 8][kk]);
                aH[mt][2] = *reinterpret_cast<const unsigned*>(&sm[0][r    ][kk + 8]);
                aH[mt][3] = *reinterpret_cast<const unsigned*>(&sm[0][r + 8][kk + 8]);
                aL[mt][0] = *reinterpret_cast<const unsigned*>(&sm[1][r    ][kk]);
                aL[mt][1] = *reinterpret_cast<const unsigned*>(&sm[1][r + 8][kk]);
                aL[mt][2] = *reinterpret_cast<const unsigned*>(&sm[1][r    ][kk + 8]);
                aL[mt][3] = *reinterpret_cast<const unsigned*>(&sm[1][r + 8][kk + 8]);
            }
            #pragma unroll
            for (int nt = 0; nt < 4; nt++) {
                const int c = wn * 32 + nt * 8 + (lane >> 2);
                bH[nt][0] = *reinterpret_cast<const unsigned*>(&sm[2][c][kk]);
                bH[nt][1] = *reinterpret_cast<const unsigned*>(&sm[2][c][kk + 8]);
                bL[nt][0] = *reinterpret_cast<const unsigned*>(&sm[3][c][kk]);
                bL[nt][1] = *reinterpret_cast<const unsigned*>(&sm[3][c][kk + 8]);
            }
            #pragma unroll
            for (int mt = 0; mt < 2; mt++)
                #pragma unroll
                for (int nt = 0; nt < 4; nt++) {
                    MMA_BF16(acc[mt][nt], aH[mt], bH[nt]);
                    MMA_BF16(acc[mt][nt], aH[mt], bL[nt]);
                    MMA_BF16(acc[mt][nt], aL[mt], bH[nt]);
                }
        }
        __syncthreads();
        if (kt + 1 < KT) {
            tile_sstore(pf, sm, tid);
            __syncthreads();
        }
    }

    // Epilogue
    #pragma unroll
    for (int mt = 0; mt < 2; mt++) {
        #pragma unroll
        for (int nt = 0; nt < 4; nt++) {
            const int m = bm0 + wm * 32 + mt * 16 + (lane >> 2);
            const int n = bn0 + wn * 32 + nt * 8 + (lane & 3) * 2;
            #pragma unroll
            for (int half = 0; half < 2; half++) {
                const int mr = m + half * 8;
                float v0 = acc[mt][nt][half * 2 + 0];
                float v1 = acc[mt][nt][half * 2 + 1];
                if (MODE == 0) {
                    v0 *= scale; v1 *= scale;
                    if (mr < bias_rows) { v0 += bias[n]; v1 += bias[n + 1]; }
                    *reinterpret_cast<float2*>(Cf + (size_t)mr * N + n) = make_float2(v0, v1);
                    union { __nv_bfloat16 b[2]; unsigned u; } H, L;
                    bf_split(v0, H.b[0], L.b[0]);
                    bf_split(v1, H.b[1], L.b[1]);
                    *reinterpret_cast<unsigned*>(Chi + (size_t)mr * N + n) = H.u;
                    *reinterpret_cast<unsigned*>(Clo + (size_t)mr * N + n) = L.u;
                } else {
                    float* dst = Cf + (size_t)blockIdx.z * M * N + (size_t)mr * N + n;
                    *reinterpret_cast<float2*>(dst) = make_float2(v0, v1);
                }
            }
        }
    }
}

// -------------------- k3: logits + 3-way softmax -> (w0, w2) ----------------
__global__ __launch_bounds__(256) void softmax_w_kernel(
    const float* __restrict__ pw, const float* __restrict__ pb)
{
    const int warp = threadIdx.x >> 5, lane = threadIdx.x & 31;
    const int b = blockIdx.x * 8 + warp;
    float s0 = 0.f, s1 = 0.f, s2 = 0.f;
    for (int e = lane; e < DRED; e += 32) {
        const float r = g_capr[b * DRED + e];
        s0 = fmaf(r, pw[0 * DRED + e], s0);
        s1 = fmaf(r, pw[1 * DRED + e], s1);
        s2 = fmaf(r, pw[2 * DRED + e], s2);
    }
    #pragma unroll
    for (int o = 16; o; o >>= 1) {
        s0 += __shfl_down_sync(0xffffffffu, s0, o);
        s1 += __shfl_down_sync(0xffffffffu, s1, o);
        s2 += __shfl_down_sync(0xffffffffu, s2, o);
    }
    if (lane == 0) {
        s0 += pb[0]; s1 += pb[1]; s2 += pb[2];
        const float m = fmaxf(s0, fmaxf(s1, s2));
        const float e0 = expf(s0 - m), e1 = expf(s1 - m), e2 = expf(s2 - m);
        const float inv = 1.f / (e0 + e1 + e2);
        g_w[b] = make_float2(e0 * inv, e2 * inv);
    }
}

// -------------------- k6: per-image 3x3 Gram of {P,Q,R} ---------------------
__global__ __launch_bounds__(256) void gram_kernel()
{
    __shared__ float smem[32];
    const int i = blockIdx.x;
    float pp = 0, qq = 0, rr = 0, pq = 0, pr = 0, qr = 0;
    for (int d = threadIdx.x; d < DIM; d += 256) {
        const float p = g_Yf[(size_t)(0 * N_IMG + i) * DIM + d];
        const float q = g_Yf[(size_t)(1 * N_IMG + i) * DIM + d];
        const float r = g_Yf[(size_t)(2 * N_IMG + i) * DIM + d];
        pp = fmaf(p, p, pp); qq = fmaf(q, q, qq); rr = fmaf(r, r, rr);
        pq = fmaf(p, q, pq); pr = fmaf(p, r, pr); qr = fmaf(q, r, qr);
    }
    pp = block_reduce_sum(pp, smem);
    qq = block_reduce_sum(qq, smem);
    rr = block_reduce_sum(rr, smem);
    pq = block_reduce_sum(pq, smem);
    pr = block_reduce_sum(pr, smem);
    qr = block_reduce_sum(qr, smem);
    if (threadIdx.x == 0) {
        float* g = &g_gram[i * 6];
        g[0] = pp; g[1] = qq; g[2] = rr; g[3] = pq; g[4] = pr; g[5] = qr;
    }
}

// -------------------- k8: combine everything into sims ----------------------
__global__ __launch_bounds__(256) void final_kernel(float* __restrict__ out)
{
    const int i = blockIdx.x, b = threadIdx.x;
    const float2 w = g_w[b];
    float zp = 0.f, zq = 0.f, zr = 0.f;
    #pragma unroll
    for (int s = 0; s < NSPLIT; s++) {
        const float* Zs = g_Zpart + (size_t)s * MROWS * N_CAP;
        zp += Zs[(size_t)(0 * N_IMG + i) * N_CAP + b];
        zq += Zs[(size_t)(1 * N_IMG + i) * N_CAP + b];
        zr += Zs[(size_t)(2 * N_IMG + i) * N_CAP + b];
    }
    const float* g = &g_gram[i * 6];
    const float numer = zp - w.x * zq - w.y * zr;
    const float den2 = g[0] + w.x * w.x * g[1] + w.y * w.y * g[2]
                     - 2.f * w.x * g[3] - 2.f * w.y * g[4] + 2.f * w.x * w.y * g[5];
    out[(size_t)i * N_CAP + b] = numer / (sqrtf(fmaxf(den2, 0.f)) + 1e-8f);
}

// -------------------- launch -------------------------------------------------
extern "C" void kernel_launch(void* const* d_in, const int* in_sizes, int n_in,
                              void* d_out, int out_size)
{
    const float* img    = (const float*)d_in[0];
    const float* cap    = (const float*)d_in[1];
    const int*   lens   = (const int*)  d_in[2];
    const float* red_w  = (const float*)d_in[3];
    const float* red_b  = (const float*)d_in[4];
    const float* proj_w = (const float*)d_in[5];
    const float* proj_b = (const float*)d_in[6];
    const float* conv_w = (const float*)d_in[7];
    const float* conv_b = (const float*)d_in[8];
    float* out = (float*)d_out;

    float *pCF, *pCR, *pYf, *pZ;
    __nv_bfloat16 *pCVh, *pCVl, *pXh, *pXl, *pWh, *pWl, *pYh, *pYl;
    cudaGetSymbolAddress((void**)&pCF,  g_capfull);
    cudaGetSymbolAddress((void**)&pCR,  g_capr);
    cudaGetSymbolAddress((void**)&pYf,  g_Yf);
    cudaGetSymbolAddress((void**)&pZ,   g_Zpart);
    cudaGetSymbolAddress((void**)&pCVh, g_cv_hi);
    cudaGetSymbolAddress((void**)&pCVl, g_cv_lo);
    cudaGetSymbolAddress((void**)&pXh,  g_X_hi);
    cudaGetSymbolAddress((void**)&pXl,  g_X_lo);
    cudaGetSymbolAddress((void**)&pWh,  g_W_hi);
    cudaGetSymbolAddress((void**)&pWl,  g_W_lo);
    cudaGetSymbolAddress((void**)&pYh,  g_Y_hi);
    cudaGetSymbolAddress((void**)&pYl,  g_Y_lo);

    // Caption branch
    cap_reduce_kernel<<<N_CAP, 256>>>(cap, lens);
    gemm_nt<32, 32, 32, 2, 2><<<dim3(DRED / 32, N_CAP / 32), 256>>>(
        pCF, red_w, pCR, N_CAP, DRED, DIM, 1.f, red_b);
    softmax_w_kernel<<<N_CAP / 8, 256>>>(proj_w, proj_b);

    // Image branch producers
    wsplit_kernel<<<(DIM * DIM / 4) / 256, 256>>>(conv_w);
    img_reduce_kernel<<<N_IMG, 256>>>(img);

    // conv GEMM (tensor cores): Y = X @ conv_w^T / 36 (+bias on P rows)
    mma_gemm_nt<0><<<dim3(DIM / GBN, MROWS / GBM, 1), 128>>>(
        pXh, pXl, pWh, pWl, pYf, pYh, pYl,
        MROWS, DIM, DIM, DIM, 1.f / (float)LREG, conv_b, N_IMG);

    gram_kernel<<<N_IMG, 256>>>();

    // Z GEMM (tensor cores, split-K=4, deterministic partials)
    mma_gemm_nt<1><<<dim3(N_CAP / GBN, MROWS / GBM, NSPLIT), 128>>>(
        pYh, pYl, pCVh, pCVl, pZ, nullptr, nullptr,
        MROWS, N_CAP, DIM, DIM / NSPLIT, 1.f, nullptr, 0);

    final_kernel<<<N_IMG, 256>>>(out);
}

// round 4
// speedup vs baseline: 1.7835x; 1.1324x over previous
#include <cuda_runtime.h>
#include <cuda_bf16.h>
#include <math.h>
#include <stdint.h>
#include <stddef.h>

// Problem dims (fixed by the dataset)
constexpr int N_IMG = 256;
constexpr int N_CAP = 256;
constexpr int T_WORDS = 64;
constexpr int DIM = 1024;
constexpr int DRED = 256;
constexpr int LREG = 36;
constexpr int MROWS = 3 * N_IMG;   // 768
constexpr int CONV_SPLIT = 4;
constexpr int Z_SPLIT = 8;

// -------------------- scratch (device globals) -------------------------------
__device__ __nv_bfloat16 g_cv_hi[N_CAP * DIM];
__device__ __nv_bfloat16 g_cv_lo[N_CAP * DIM];
__device__ float2        g_w    [N_CAP];
__device__ __nv_bfloat16 g_X_hi [MROWS * DIM];
__device__ __nv_bfloat16 g_X_lo [MROWS * DIM];
__device__ __nv_bfloat16 g_W_hi [DIM * DIM];
__device__ __nv_bfloat16 g_W_lo [DIM * DIM];
__device__ __nv_bfloat16 g_Y_hi [MROWS * DIM];
__device__ __nv_bfloat16 g_Y_lo [MROWS * DIM];
__device__ float         g_q    [3 * DIM];
__device__ float         g_cb   [3];
__device__ float         g_Ypart[CONV_SPLIT * MROWS * DIM];
__device__ float         g_Zpart[Z_SPLIT * MROWS * N_CAP];
__device__ float         g_gram [N_IMG * 6];

// -------------------- small helpers -----------------------------------------
__device__ __forceinline__ float blk_sum(float v, float* s32) {
    __syncthreads();
    const int lane = threadIdx.x & 31, warp = threadIdx.x >> 5;
    const int nw = blockDim.x >> 5;
    #pragma unroll
    for (int o = 16; o; o >>= 1) v += __shfl_down_sync(0xffffffffu, v, o);
    if (lane == 0) s32[warp] = v;
    __syncthreads();
    if (warp == 0) {
        v = (lane < nw) ? s32[lane] : 0.f;
        #pragma unroll
        for (int o = 16; o; o >>= 1) v += __shfl_down_sync(0xffffffffu, v, o);
        if (lane == 0) s32[0] = v;
    }
    __syncthreads();
    return s32[0];
}

__device__ __forceinline__ void bf_split(float x, __nv_bfloat16& h, __nv_bfloat16& l) {
    h = __float2bfloat16(x);
    l = __float2bfloat16(x - __bfloat162float(h));
}

__device__ __forceinline__ void split_store4(__nv_bfloat16* hi, __nv_bfloat16* lo,
                                             size_t idx, float4 v) {
    union { __nv_bfloat16 b[4]; uint2 u; } H, L;
    bf_split(v.x, H.b[0], L.b[0]); bf_split(v.y, H.b[1], L.b[1]);
    bf_split(v.z, H.b[2], L.b[2]); bf_split(v.w, H.b[3], L.b[3]);
    *reinterpret_cast<uint2*>(hi + idx) = H.u;
    *reinterpret_cast<uint2*>(lo + idx) = L.u;
}

__device__ __forceinline__ float4 f4add(float4 a, float4 b) {
    return make_float4(a.x + b.x, a.y + b.y, a.z + b.z, a.w + b.w);
}
__device__ __forceinline__ float f4dot(float4 a, float4 b) {
    return a.x * b.x + a.y * b.y + a.z * b.z + a.w * b.w;
}

// -------------------- k0: q = proj_w @ red_w, cb = proj_b + proj_w@red_b ----
__global__ __launch_bounds__(256) void qprep_kernel(
    const float* __restrict__ red_w, const float* __restrict__ red_b,
    const float* __restrict__ proj_w, const float* __restrict__ proj_b)
{
    const int d = blockIdx.x * 256 + threadIdx.x;
    float l0 = 0.f, l1 = 0.f, l2 = 0.f;
    for (int e = 0; e < DRED; e++) {
        const float r = red_w[(size_t)e * DIM + d];
        l0 = fmaf(r, proj_w[e],            l0);
        l1 = fmaf(r, proj_w[DRED + e],     l1);
        l2 = fmaf(r, proj_w[2 * DRED + e], l2);
    }
    g_q[d]            = l0;
    g_q[DIM + d]      = l1;
    g_q[2 * DIM + d]  = l2;
    if (blockIdx.x == 0 && threadIdx.x < 3) {
        const int k = threadIdx.x;
        float c = proj_b[k];
        for (int e = 0; e < DRED; e++) c = fmaf(red_b[e], proj_w[k * DRED + e], c);
        g_cb[k] = c;
    }
}

// -------------------- k1: caption mean + l2norm + logits + softmax ----------
__global__ __launch_bounds__(1024) void cap_fused_kernel(
    const float* __restrict__ cap, const int* __restrict__ lens)
{
    __shared__ float4 part[4][256];
    __shared__ float s32[32];
    const int b = blockIdx.x;
    const int tid = threadIdx.x;
    const int chunk = tid >> 8;        // 0..3 (16 words each)
    const int lane4 = tid & 255;       // float4 lane over D
    const int len = lens[b];
    const float4* c4 = reinterpret_cast<const float4*>(cap) + (size_t)b * (T_WORDS * DIM / 4);

    float4 a = make_float4(0.f, 0.f, 0.f, 0.f);
    const int t0 = chunk * 16;
    const int t1 = min(len, t0 + 16);
    for (int t = t0; t < t1; t++) a = f4add(a, c4[t * (DIM / 4) + lane4]);
    part[chunk][lane4] = a;
    __syncthreads();

    float ss = 0.f, l0 = 0.f, l1 = 0.f, l2 = 0.f;
    float4 cf = make_float4(0.f, 0.f, 0.f, 0.f);
    if (chunk == 0) {
        cf = f4add(f4add(part[0][lane4], part[1][lane4]),
                   f4add(part[2][lane4], part[3][lane4]));
        const float inv = 1.f / (float)len;
        cf.x *= inv; cf.y *= inv; cf.z *= inv; cf.w *= inv;
        ss = f4dot(cf, cf);
        const float4 q0 = reinterpret_cast<const float4*>(g_q)[lane4];
        const float4 q1 = reinterpret_cast<const float4*>(g_q + DIM)[lane4];
        const float4 q2 = reinterpret_cast<const float4*>(g_q + 2 * DIM)[lane4];
        l0 = f4dot(cf, q0); l1 = f4dot(cf, q1); l2 = f4dot(cf, q2);
    }
    ss = blk_sum(ss, s32);
    l0 = blk_sum(l0, s32);
    l1 = blk_sum(l1, s32);
    l2 = blk_sum(l2, s32);

    if (tid == 0) {
        const float s0 = l0 + g_cb[0], s1 = l1 + g_cb[1], s2 = l2 + g_cb[2];
        const float m = fmaxf(s0, fmaxf(s1, s2));
        const float e0 = expf(s0 - m), e1 = expf(s1 - m), e2 = expf(s2 - m);
        const float inv = 1.f / (e0 + e1 + e2);
        g_w[b] = make_float2(e0 * inv, e2 * inv);
    }
    if (chunk == 0) {
        const float invn = 1.f / (sqrtf(ss) + 1e-8f);
        cf.x *= invn; cf.y *= invn; cf.z *= invn; cf.w *= invn;
        split_store4(g_cv_hi, g_cv_lo, (size_t)b * DIM + (size_t)lane4 * 4, cf);
    }
}

// -------------------- k2: image region sum + edge rows ----------------------
__global__ __launch_bounds__(1024) void img_reduce_kernel(const float* __restrict__ img)
{
    __shared__ float4 part[4][256];
    const int i = blockIdx.x;
    const int tid = threadIdx.x;
    const int chunk = tid >> 8;        // 0..3 (9 rows each)
    const int lane4 = tid & 255;
    const float4* p = reinterpret_cast<const float4*>(img) + (size_t)i * (LREG * DIM / 4);

    float4 s = make_float4(0.f, 0.f, 0.f, 0.f);
    float4 first = s, last = s;
    const int r0 = chunk * 9;
    #pragma unroll
    for (int r = 0; r < 9; r++) {
        const int row = r0 + r;
        float4 v = p[row * (DIM / 4) + lane4];
        if (row == 0) first = v;
        if (row == LREG - 1) last = v;
        s = f4add(s, v);
    }
    part[chunk][lane4] = s;
    __syncthreads();

    const size_t d0 = (size_t)lane4 * 4;
    if (chunk == 0) {
        float4 S = f4add(f4add(part[0][lane4], part[1][lane4]),
                         f4add(part[2][lane4], part[3][lane4]));
        split_store4(g_X_hi, g_X_lo, (size_t)(0 * N_IMG + i) * DIM + d0, S);
        split_store4(g_X_hi, g_X_lo, (size_t)(2 * N_IMG + i) * DIM + d0, first);  // row 0
    }
    if (chunk == 3) {
        split_store4(g_X_hi, g_X_lo, (size_t)(1 * N_IMG + i) * DIM + d0, last);   // row 35
    }
}

// -------------------- k3: split conv_w into bf16 hi/lo ----------------------
__global__ __launch_bounds__(256) void wsplit_kernel(const float* __restrict__ w)
{
    const int t = blockIdx.x * 256 + threadIdx.x;
    #pragma unroll
    for (int i = 0; i < 4; i++) {
        const size_t idx4 = (size_t)t + (size_t)i * 65536;
        float4 v = reinterpret_cast<const float4*>(w)[idx4];
        split_store4(g_W_hi, g_W_lo, idx4 * 4, v);
    }
}

// -------------------- tensor-core NT GEMM, split-bf16, cp.async pipeline ----
#define MMA_BF16(c, a, b)                                                      \
    asm volatile("mma.sync.aligned.m16n8k16.row.col.f32.bf16.bf16.f32 "        \
                 "{%0,%1,%2,%3}, {%4,%5,%6,%7}, {%8,%9}, {%0,%1,%2,%3};"       \
                 : "+f"((c)[0]), "+f"((c)[1]), "+f"((c)[2]), "+f"((c)[3])      \
                 : "r"((a)[0]), "r"((a)[1]), "r"((a)[2]), "r"((a)[3]),         \
                   "r"((b)[0]), "r"((b)[1]))

constexpr int GBM = 128, GBN = 64, GBK = 32, PITCH = 40, STAGES = 3;
constexpr int OFF_AH = 0;
constexpr int OFF_AL = GBM * PITCH;            // 5120
constexpr int OFF_BH = 2 * GBM * PITCH;        // 10240
constexpr int OFF_BL = OFF_BH + GBN * PITCH;   // 12800
constexpr int STAGE_ELEMS = OFF_BL + GBN * PITCH;   // 15360 bf16 = 30720 B
constexpr int MMA_SMEM_BYTES = STAGES * STAGE_ELEMS * 2;  // 92160

__device__ __forceinline__ void cp16(uint32_t d, const void* s) {
    asm volatile("cp.async.cg.shared.global [%0], [%1], 16;\n" :: "r"(d), "l"(s));
}

__device__ __forceinline__ void mma_issue_stage(
    uint32_t sb0, int slot, int tid, int k0, int K,
    const __nv_bfloat16* pAh, const __nv_bfloat16* pAl,
    const __nv_bfloat16* pBh, const __nv_bfloat16* pBl)
{
    const uint32_t sb = sb0 + (uint32_t)slot * (STAGE_ELEMS * 2);
    #pragma unroll
    for (int it = 0; it < 2; it++) {
        const int idx = tid + it * 256;
        const int row = idx >> 2, c4 = idx & 3;
        const size_t go = (size_t)row * K + k0 + c4 * 8;
        const uint32_t so = (uint32_t)row * (PITCH * 2) + c4 * 16;
        cp16(sb + OFF_AH * 2 + so, pAh + go);
        cp16(sb + OFF_AL * 2 + so, pAl + go);
    }
    {
        const int row = tid >> 2, c4 = tid & 3;
        const size_t go = (size_t)row * K + k0 + c4 * 8;
        const uint32_t so = (uint32_t)row * (PITCH * 2) + c4 * 16;
        cp16(sb + OFF_BH * 2 + so, pBh + go);
        cp16(sb + OFF_BL * 2 + so, pBl + go);
    }
    asm volatile("cp.async.commit_group;\n");
}

__global__ __launch_bounds__(256) void mma_gemm_nt(
    const __nv_bfloat16* __restrict__ Ahi, const __nv_bfloat16* __restrict__ Alo,
    const __nv_bfloat16* __restrict__ Bhi, const __nv_bfloat16* __restrict__ Blo,
    float* __restrict__ Cpart, int M, int N, int K, int KLEN)
{
    extern __shared__ __align__(16) __nv_bfloat16 smem[];
    const int tid = threadIdx.x, lane = tid & 31, warp = tid >> 5;
    const int wm = warp >> 1, wn = warp & 1;   // 4x2 warps, 32x32 each
    const int bm0 = blockIdx.y * GBM, bn0 = blockIdx.x * GBN;
    const int kbase = blockIdx.z * KLEN;
    const int KT = KLEN / GBK;

    const __nv_bfloat16* pAh = Ahi + (size_t)bm0 * K;
    const __nv_bfloat16* pAl = Alo + (size_t)bm0 * K;
    const __nv_bfloat16* pBh = Bhi + (size_t)bn0 * K;
    const __nv_bfloat16* pBl = Blo + (size_t)bn0 * K;
    const uint32_t sb0 = (uint32_t)__cvta_generic_to_shared(smem);

    float acc[2][4][4] = {};

    // Prologue: always commit STAGES-1 groups (empty beyond KT)
    #pragma unroll
    for (int s = 0; s < STAGES - 1; s++) {
        if (s < KT) mma_issue_stage(sb0, s, tid, kbase + s * GBK, K, pAh, pAl, pBh, pBl);
        else        asm volatile("cp.async.commit_group;\n");
    }

    for (int kt = 0; kt < KT; kt++) {
        asm volatile("cp.async.wait_group %0;\n" :: "n"(STAGES - 2));
        __syncthreads();
        {
            const int nx = kt + STAGES - 1;
            if (nx < KT) mma_issue_stage(sb0, nx % STAGES, tid, kbase + nx * GBK, K,
                                         pAh, pAl, pBh, pBl);
            else         asm volatile("cp.async.commit_group;\n");
        }
        const __nv_bfloat16* st = smem + (kt % STAGES) * STAGE_ELEMS;
        #pragma unroll
        for (int s = 0; s < 2; s++) {
            const int kk = s * 16 + (lane & 3) * 2;
            unsigned aH[2][4], aL[2][4], bH[4][2], bL[4][2];
            #pragma unroll
            for (int mt = 0; mt < 2; mt++) {
                const int r = wm * 32 + mt * 16 + (lane >> 2);
                aH[mt][0] = *reinterpret_cast<const unsigned*>(&st[OFF_AH + r * PITCH + kk]);
                aH[mt][1] = *reinterpret_cast<const unsigned*>(&st[OFF_AH + (r + 8) * PITCH + kk]);
                aH[mt][2] = *reinterpret_cast<const unsigned*>(&st[OFF_AH + r * PITCH + kk + 8]);
                aH[mt][3] = *reinterpret_cast<const unsigned*>(&st[OFF_AH + (r + 8) * PITCH + kk + 8]);
                aL[mt][0] = *reinterpret_cast<const unsigned*>(&st[OFF_AL + r * PITCH + kk]);
                aL[mt][1] = *reinterpret_cast<const unsigned*>(&st[OFF_AL + (r + 8) * PITCH + kk]);
                aL[mt][2] = *reinterpret_cast<const unsigned*>(&st[OFF_AL + r * PITCH + kk + 8]);
                aL[mt][3] = *reinterpret_cast<const unsigned*>(&st[OFF_AL + (r + 8) * PITCH + kk + 8]);
            }
            #pragma unroll
            for (int nt = 0; nt < 4; nt++) {
                const int c = wn * 32 + nt * 8 + (lane >> 2);
                bH[nt][0] = *reinterpret_cast<const unsigned*>(&st[OFF_BH + c * PITCH + kk]);
                bH[nt][1] = *reinterpret_cast<const unsigned*>(&st[OFF_BH + c * PITCH + kk + 8]);
                bL[nt][0] = *reinterpret_cast<const unsigned*>(&st[OFF_BL + c * PITCH + kk]);
                bL[nt][1] = *reinterpret_cast<const unsigned*>(&st[OFF_BL + c * PITCH + kk + 8]);
            }
            #pragma unroll
            for (int mt = 0; mt < 2; mt++)
                #pragma unroll
                for (int nt = 0; nt < 4; nt++) MMA_BF16(acc[mt][nt], aH[mt], bH[nt]);
            #pragma unroll
            for (int mt = 0; mt < 2; mt++)
                #pragma unroll
                for (int nt = 0; nt < 4; nt++) MMA_BF16(acc[mt][nt], aH[mt], bL[nt]);
            #pragma unroll
            for (int mt = 0; mt < 2; mt++)
                #pragma unroll
                for (int nt = 0; nt < 4; nt++) MMA_BF16(acc[mt][nt], aL[mt], bH[nt]);
        }
    }

    float* Cz = Cpart + (size_t)blockIdx.z * M * N;
    #pragma unroll
    for (int mt = 0; mt < 2; mt++) {
        #pragma unroll
        for (int nt = 0; nt < 4; nt++) {
            const int m = bm0 + wm * 32 + mt * 16 + (lane >> 2);
            const int n = bn0 + wn * 32 + nt * 8 + (lane & 3) * 2;
            #pragma unroll
            for (int half = 0; half < 2; half++) {
                *reinterpret_cast<float2*>(Cz + (size_t)(m + half * 8) * N + n) =
                    make_float2(acc[mt][nt][half * 2], acc[mt][nt][half * 2 + 1]);
            }
        }
    }
}

// -------------------- k5: combine conv partials + bias + split + gram -------
__global__ __launch_bounds__(256) void combine_gram_kernel(const float* __restrict__ conv_b)
{
    __shared__ float s32[32];
    const int i = blockIdx.x, t = threadIdx.x;
    const float sc = 1.f / (float)LREG;

    float4 ap = make_float4(0.f, 0.f, 0.f, 0.f), aq = ap, ar = ap;
    #pragma unroll
    for (int z = 0; z < CONV_SPLIT; z++) {
        const float4* Pz = reinterpret_cast<const float4*>(g_Ypart + (size_t)z * MROWS * DIM);
        ap = f4add(ap, Pz[(size_t)(0 * N_IMG + i) * (DIM / 4) + t]);
        aq = f4add(aq, Pz[(size_t)(1 * N_IMG + i) * (DIM / 4) + t]);
        ar = f4add(ar, Pz[(size_t)(2 * N_IMG + i) * (DIM / 4) + t]);
    }
    const float4 b4 = reinterpret_cast<const float4*>(conv_b)[t];
    float4 yp = make_float4(ap.x * sc + b4.x, ap.y * sc + b4.y,
                            ap.z * sc + b4.z, ap.w * sc + b4.w);
    float4 yq = make_float4(aq.x * sc, aq.y * sc, aq.z * sc, aq.w * sc);
    float4 yr = make_float4(ar.x * sc, ar.y * sc, ar.z * sc, ar.w * sc);

    const size_t d0 = (size_t)t * 4;
    split_store4(g_Y_hi, g_Y_lo, (size_t)(0 * N_IMG + i) * DIM + d0, yp);
    split_store4(g_Y_hi, g_Y_lo, (size_t)(1 * N_IMG + i) * DIM + d0, yq);
    split_store4(g_Y_hi, g_Y_lo, (size_t)(2 * N_IMG + i) * DIM + d0, yr);

    float pp = f4dot(yp, yp), qq = f4dot(yq, yq), rr = f4dot(yr, yr);
    float pq = f4dot(yp, yq), pr = f4dot(yp, yr), qr = f4dot(yq, yr);
    pp = blk_sum(pp, s32); qq = blk_sum(qq, s32); rr = blk_sum(rr, s32);
    pq = blk_sum(pq, s32); pr = blk_sum(pr, s32); qr = blk_sum(qr, s32);
    if (t == 0) {
        float* g = &g_gram[i * 6];
        g[0] = pp; g[1] = qq; g[2] = rr; g[3] = pq; g[4] = pr; g[5] = qr;
    }
}

// -------------------- k7: combine Z partials + final sims -------------------
__global__ __launch_bounds__(256) void final_kernel(float* __restrict__ out)
{
    const int i = blockIdx.x, b = threadIdx.x;
    const float2 w = g_w[b];
    float zp = 0.f, zq = 0.f, zr = 0.f;
    #pragma unroll
    for (int s = 0; s < Z_SPLIT; s++) {
        const float* Zs = g_Zpart + (size_t)s * MROWS * N_CAP;
        zp += Zs[(size_t)(0 * N_IMG + i) * N_CAP + b];
        zq += Zs[(size_t)(1 * N_IMG + i) * N_CAP + b];
        zr += Zs[(size_t)(2 * N_IMG + i) * N_CAP + b];
    }
    const float* g = &g_gram[i * 6];
    const float numer = zp - w.x * zq - w.y * zr;
    const float den2 = g[0] + w.x * w.x * g[1] + w.y * w.y * g[2]
                     - 2.f * w.x * g[3] - 2.f * w.y * g[4] + 2.f * w.x * w.y * g[5];
    out[(size_t)i * N_CAP + b] = numer / (sqrtf(fmaxf(den2, 0.f)) + 1e-8f);
}

// -------------------- launch -------------------------------------------------
extern "C" void kernel_launch(void* const* d_in, const int* in_sizes, int n_in,
                              void* d_out, int out_size)
{
    const float* img    = (const float*)d_in[0];
    const float* cap    = (const float*)d_in[1];
    const int*   lens   = (const int*)  d_in[2];
    const float* red_w  = (const float*)d_in[3];
    const float* red_b  = (const float*)d_in[4];
    const float* proj_w = (const float*)d_in[5];
    const float* proj_b = (const float*)d_in[6];
    const float* conv_w = (const float*)d_in[7];
    const float* conv_b = (const float*)d_in[8];
    float* out = (float*)d_out;

    __nv_bfloat16 *pCVh, *pCVl, *pXh, *pXl, *pWh, *pWl, *pYh, *pYl;
    float *pYp, *pZp;
    cudaGetSymbolAddress((void**)&pCVh, g_cv_hi);
    cudaGetSymbolAddress((void**)&pCVl, g_cv_lo);
    cudaGetSymbolAddress((void**)&pXh,  g_X_hi);
    cudaGetSymbolAddress((void**)&pXl,  g_X_lo);
    cudaGetSymbolAddress((void**)&pWh,  g_W_hi);
    cudaGetSymbolAddress((void**)&pWl,  g_W_lo);
    cudaGetSymbolAddress((void**)&pYh,  g_Y_hi);
    cudaGetSymbolAddress((void**)&pYl,  g_Y_lo);
    cudaGetSymbolAddress((void**)&pYp,  g_Ypart);
    cudaGetSymbolAddress((void**)&pZp,  g_Zpart);

    cudaFuncSetAttribute(mma_gemm_nt, cudaFuncAttributeMaxDynamicSharedMemorySize,
                         MMA_SMEM_BYTES);

    // Caption branch
    qprep_kernel<<<DIM / 256, 256>>>(red_w, red_b, proj_w, proj_b);
    cap_fused_kernel<<<N_CAP, 1024>>>(cap, lens);

    // Image branch producers
    wsplit_kernel<<<256, 256>>>(conv_w);
    img_reduce_kernel<<<N_IMG, 1024>>>(img);

    // conv GEMM: Ypart[z] = X @ conv_w^T (partial over K), split-K=4
    mma_gemm_nt<<<dim3(DIM / GBN, MROWS / GBM, CONV_SPLIT), 256, MMA_SMEM_BYTES>>>(
        pXh, pXl, pWh, pWl, pYp, MROWS, DIM, DIM, DIM / CONV_SPLIT);

    // combine partials, bias+scale, bf16 split of Y, fused per-image Gram
    combine_gram_kernel<<<N_IMG, 256>>>(conv_b);

    // Z GEMM: Zpart[z] = Y @ cap_v^T (partial over K), split-K=8
    mma_gemm_nt<<<dim3(N_CAP / GBN, MROWS / GBM, Z_SPLIT), 256, MMA_SMEM_BYTES>>>(
        pYh, pYl, pCVh, pCVl, pZp, MROWS, N_CAP, DIM, DIM / Z_SPLIT);

    final_kernel<<<N_IMG, 256>>>(out);
}

// round 6
// speedup vs baseline: 1.7973x; 1.0077x over previous
#include <cuda_runtime.h>
#include <cuda_bf16.h>
#include <math.h>
#include <stdint.h>
#include <stddef.h>

// Problem dims (fixed by the dataset)
constexpr int N_IMG = 256;
constexpr int N_CAP = 256;
constexpr int T_WORDS = 64;
constexpr int DIM = 1024;
constexpr int DRED = 256;
constexpr int LREG = 36;
constexpr int MROWS = 3 * N_IMG;   // 768
constexpr int CONV_SPLIT = 4;      // KLEN 256
constexpr int Z_SPLIT = 16;        // KLEN 64

// -------------------- scratch (device globals) -------------------------------
__device__ __nv_bfloat16 g_cv_hi[N_CAP * DIM];
__device__ __nv_bfloat16 g_cv_lo[N_CAP * DIM];
__device__ float2        g_w    [N_CAP];
__device__ __nv_bfloat16 g_X_hi [MROWS * DIM];
__device__ __nv_bfloat16 g_X_lo [MROWS * DIM];
__device__ __nv_bfloat16 g_W_hi [DIM * DIM];
__device__ __nv_bfloat16 g_W_lo [DIM * DIM];
__device__ __nv_bfloat16 g_Y_hi [MROWS * DIM];
__device__ __nv_bfloat16 g_Y_lo [MROWS * DIM];
__device__ float         g_q    [3 * DIM];
__device__ float         g_cb   [3];
__device__ float         g_Ypart[CONV_SPLIT * MROWS * DIM];
__device__ float         g_Zpart[Z_SPLIT * MROWS * N_CAP];
__device__ float         g_gram [N_IMG * 6];

// -------------------- small helpers -----------------------------------------
__device__ __forceinline__ float blk_sum(float v, float* s32) {
    __syncthreads();
    const int lane = threadIdx.x & 31, warp = threadIdx.x >> 5;
    const int nw = blockDim.x >> 5;
    #pragma unroll
    for (int o = 16; o; o >>= 1) v += __shfl_down_sync(0xffffffffu, v, o);
    if (lane == 0) s32[warp] = v;
    __syncthreads();
    if (warp == 0) {
        v = (lane < nw) ? s32[lane] : 0.f;
        #pragma unroll
        for (int o = 16; o; o >>= 1) v += __shfl_down_sync(0xffffffffu, v, o);
        if (lane == 0) s32[0] = v;
    }
    __syncthreads();
    return s32[0];
}

__device__ __forceinline__ void bf_split(float x, __nv_bfloat16& h, __nv_bfloat16& l) {
    h = __float2bfloat16(x);
    l = __float2bfloat16(x - __bfloat162float(h));
}

__device__ __forceinline__ void split_store4(__nv_bfloat16* hi, __nv_bfloat16* lo,
                                             size_t idx, float4 v) {
    union { __nv_bfloat16 b[4]; uint2 u; } H, L;
    bf_split(v.x, H.b[0], L.b[0]); bf_split(v.y, H.b[1], L.b[1]);
    bf_split(v.z, H.b[2], L.b[2]); bf_split(v.w, H.b[3], L.b[3]);
    *reinterpret_cast<uint2*>(hi + idx) = H.u;
    *reinterpret_cast<uint2*>(lo + idx) = L.u;
}

__device__ __forceinline__ float4 f4add(float4 a, float4 b) {
    return make_float4(a.x + b.x, a.y + b.y, a.z + b.z, a.w + b.w);
}
__device__ __forceinline__ float f4dot(float4 a, float4 b) {
    return a.x * b.x + a.y * b.y + a.z * b.z + a.w * b.w;
}

// ===== k0: fused producers: qprep (4 blocks) + wsplit (256) + img (256) =====
__global__ __launch_bounds__(256) void producers_kernel(
    const float* __restrict__ img, const float* __restrict__ red_w,
    const float* __restrict__ red_b, const float* __restrict__ proj_w,
    const float* __restrict__ proj_b, const float* __restrict__ conv_w)
{
    const int b = blockIdx.x, t = threadIdx.x;
    if (b < 4) {
        // q = proj_w @ red_w (per output dim d); cb = proj_b + proj_w @ red_b
        const int d = b * 256 + t;
        float l0 = 0.f, l1 = 0.f, l2 = 0.f;
        for (int e = 0; e < DRED; e++) {
            const float r = red_w[(size_t)e * DIM + d];
            l0 = fmaf(r, proj_w[e],            l0);
            l1 = fmaf(r, proj_w[DRED + e],     l1);
            l2 = fmaf(r, proj_w[2 * DRED + e], l2);
        }
        g_q[d]           = l0;
        g_q[DIM + d]     = l1;
        g_q[2 * DIM + d] = l2;
        if (b == 0 && t < 3) {
            float c = proj_b[t];
            for (int e = 0; e < DRED; e++) c = fmaf(red_b[e], proj_w[t * DRED + e], c);
            g_cb[t] = c;
        }
    } else if (b < 260) {
        // split conv_w into bf16 hi/lo
        const int bi = b - 4;
        #pragma unroll
        for (int i = 0; i < 4; i++) {
            const size_t idx4 = (size_t)bi * 256 + t + (size_t)i * 65536;
            float4 v = reinterpret_cast<const float4*>(conv_w)[idx4];
            split_store4(g_W_hi, g_W_lo, idx4 * 4, v);
        }
    } else {
        // image region sum + edge rows
        const int i = b - 260;
        const float4* p = reinterpret_cast<const float4*>(img) + (size_t)i * (LREG * DIM / 4);
        float4 s = make_float4(0.f, 0.f, 0.f, 0.f);
        float4 r0 = s, rl = s;
        #pragma unroll
        for (int l = 0; l < LREG; l++) {
            float4 v = p[l * (DIM / 4) + t];
            if (l == 0) r0 = v;
            if (l == LREG - 1) rl = v;
            s = f4add(s, v);
        }
        const size_t d0 = (size_t)t * 4;
        split_store4(g_X_hi, g_X_lo, (size_t)(0 * N_IMG + i) * DIM + d0, s);
        split_store4(g_X_hi, g_X_lo, (size_t)(1 * N_IMG + i) * DIM + d0, rl);
        split_store4(g_X_hi, g_X_lo, (size_t)(2 * N_IMG + i) * DIM + d0, r0);
    }
}

// -------------------- k1: caption mean + l2norm + logits + softmax ----------
__global__ __launch_bounds__(1024) void cap_fused_kernel(
    const float* __restrict__ cap, const int* __restrict__ lens)
{
    __shared__ float4 part[4][256];
    __shared__ float s32[32];
    const int b = blockIdx.x;
    const int tid = threadIdx.x;
    const int chunk = tid >> 8;
    const int lane4 = tid & 255;
    const int len = lens[b];
    const float4* c4 = reinterpret_cast<const float4*>(cap) + (size_t)b * (T_WORDS * DIM / 4);

    float4 a = make_float4(0.f, 0.f, 0.f, 0.f);
    const int t0 = chunk * 16;
    const int t1 = min(len, t0 + 16);
    for (int t = t0; t < t1; t++) a = f4add(a, c4[t * (DIM / 4) + lane4]);
    part[chunk][lane4] = a;
    __syncthreads();

    float ss = 0.f, l0 = 0.f, l1 = 0.f, l2 = 0.f;
    float4 cf = make_float4(0.f, 0.f, 0.f, 0.f);
    if (chunk == 0) {
        cf = f4add(f4add(part[0][lane4], part[1][lane4]),
                   f4add(part[2][lane4], part[3][lane4]));
        const float inv = 1.f / (float)len;
        cf.x *= inv; cf.y *= inv; cf.z *= inv; cf.w *= inv;
        ss = f4dot(cf, cf);
        const float4 q0 = reinterpret_cast<const float4*>(g_q)[lane4];
        const float4 q1 = reinterpret_cast<const float4*>(g_q + DIM)[lane4];
        const float4 q2 = reinterpret_cast<const float4*>(g_q + 2 * DIM)[lane4];
        l0 = f4dot(cf, q0); l1 = f4dot(cf, q1); l2 = f4dot(cf, q2);
    }
    ss = blk_sum(ss, s32);
    l0 = blk_sum(l0, s32);
    l1 = blk_sum(l1, s32);
    l2 = blk_sum(l2, s32);

    if (tid == 0) {
        const float s0 = l0 + g_cb[0], s1 = l1 + g_cb[1], s2 = l2 + g_cb[2];
        const float m = fmaxf(s0, fmaxf(s1, s2));
        const float e0 = expf(s0 - m), e1 = expf(s1 - m), e2 = expf(s2 - m);
        const float inv = 1.f / (e0 + e1 + e2);
        g_w[b] = make_float2(e0 * inv, e2 * inv);
    }
    if (chunk == 0) {
        const float invn = 1.f / (sqrtf(ss) + 1e-8f);
        cf.x *= invn; cf.y *= invn; cf.z *= invn; cf.w *= invn;
        split_store4(g_cv_hi, g_cv_lo, (size_t)b * DIM + (size_t)lane4 * 4, cf);
    }
}

// ============ HMMA NT GEMM: ldmatrix + cp.async double buffer ================
// C[m,n] = sum_k A[m,k]*B[n,k]; A/B split-bf16 (3 accumulating terms).
// CTA tile 128x128, k-tile 64; 8 warps (2x4), warp tile 64x32.
// Cpart[z][m][n] = partial over K-chunk z = blockIdx.z.

#define MMA_BF16(c, a, b0r, b1r)                                               \
    asm volatile("mma.sync.aligned.m16n8k16.row.col.f32.bf16.bf16.f32 "        \
                 "{%0,%1,%2,%3}, {%4,%5,%6,%7}, {%8,%9}, {%0,%1,%2,%3};"       \
                 : "+f"((c)[0]), "+f"((c)[1]), "+f"((c)[2]), "+f"((c)[3])      \
                 : "r"((a)[0]), "r"((a)[1]), "r"((a)[2]), "r"((a)[3]),         \
                   "r"(b0r), "r"(b1r))

#define LDSM_X4(r, addr)                                                       \
    asm volatile("ldmatrix.sync.aligned.m8n8.x4.shared.b16 {%0,%1,%2,%3}, [%4];" \
                 : "=r"((r)[0]), "=r"((r)[1]), "=r"((r)[2]), "=r"((r)[3])      \
                 : "r"(addr))

constexpr int CTM = 128, CTN = 128, CTK = 64;
constexpr uint32_t ST_A_H = 0;
constexpr uint32_t ST_A_L = 16384;
constexpr uint32_t ST_B_H = 32768;
constexpr uint32_t ST_B_L = 49152;
constexpr uint32_t STAGE_BYTES = 65536;
constexpr int GEMM_SMEM = 2 * STAGE_BYTES;   // 128 KB

__device__ __forceinline__ void cp16(uint32_t d, const void* s) {
    asm volatile("cp.async.cg.shared.global [%0], [%1], 16;\n" :: "r"(d), "l"(s));
}

// swizzled byte offset of 16B chunk (row r, chunk c in 0..7) in a 128x64 tile
__device__ __forceinline__ uint32_t swz(int r, int c) {
    return (uint32_t)(r * 128 + ((c ^ (r & 7)) << 4));
}

__device__ __forceinline__ void gemm_load_stage(
    uint32_t sb, int tid, int k0, int K,
    const __nv_bfloat16* Ah, const __nv_bfloat16* Al,
    const __nv_bfloat16* Bh, const __nv_bfloat16* Bl)
{
    #pragma unroll
    for (int i = 0; i < 4; i++) {
        const int idx = tid + i * 256;
        const int r = idx >> 3, c = idx & 7;
        const size_t go = (size_t)r * K + k0 + c * 8;
        const uint32_t so = swz(r, c);
        cp16(sb + ST_A_H + so, Ah + go);
        cp16(sb + ST_A_L + so, Al + go);
        cp16(sb + ST_B_H + so, Bh + go);
        cp16(sb + ST_B_L + so, Bl + go);
    }
    asm volatile("cp.async.commit_group;\n");
}

__global__ __launch_bounds__(256, 1) void hmma_gemm(
    const __nv_bfloat16* __restrict__ Ahi, const __nv_bfloat16* __restrict__ Alo,
    const __nv_bfloat16* __restrict__ Bhi, const __nv_bfloat16* __restrict__ Blo,
    float* __restrict__ Cpart, int Nc, int Mtot, int K, int KLEN)
{
    extern __shared__ __align__(16) char smem[];
    const uint32_t sb0 = (uint32_t)__cvta_generic_to_shared(smem);
    const int tid = threadIdx.x, lane = tid & 31, warp = tid >> 5;
    const int wm = warp >> 2, wn = warp & 3;          // 2 x 4 warps
    const int bm0 = blockIdx.y * CTM, bn0 = blockIdx.x * CTN;
    const int kbase = blockIdx.z * KLEN;
    const int KT = KLEN / CTK;

    const __nv_bfloat16* pAh = Ahi + (size_t)bm0 * K;
    const __nv_bfloat16* pAl = Alo + (size_t)bm0 * K;
    const __nv_bfloat16* pBh = Bhi + (size_t)bn0 * K;
    const __nv_bfloat16* pBl = Blo + (size_t)bn0 * K;

    float acc[4][4][4] = {};

    // lane -> ldmatrix tile addressing
    const int tl = lane >> 3, ri = lane & 7;          // tile index, row within tile
    const int trow = ((tl & 1) << 3) + ri;            // +0/+8 row
    const int tch  = tl >> 1;                         // +0/+1 chunk

    gemm_load_stage(sb0, tid, kbase, K, pAh, pAl, pBh, pBl);

    for (int kt = 0; kt < KT; kt++) {
        const int nx = kt + 1;
        if (nx < KT)
            gemm_load_stage(sb0 + (nx & 1) * STAGE_BYTES, tid, kbase + nx * CTK, K,
                            pAh, pAl, pBh, pBl);
        else
            asm volatile("cp.async.commit_group;\n");
        asm volatile("cp.async.wait_group 1;\n" ::: "memory");
        __syncthreads();

        const uint32_t st = sb0 + (kt & 1) * STAGE_BYTES;
        #pragma unroll
        for (int s16 = 0; s16 < 4; s16++) {
            const int c0 = s16 * 2 + tch;
            uint32_t aH[4][4], aL[4][4], bH[2][4], bL[2][4];
            #pragma unroll
            for (int mt = 0; mt < 4; mt++) {
                const int r = wm * 64 + mt * 16 + trow;
                LDSM_X4(aH[mt], st + ST_A_H + swz(r, c0));
                LDSM_X4(aL[mt], st + ST_A_L + swz(r, c0));
            }
            #pragma unroll
            for (int g = 0; g < 2; g++) {
                const int r = wn * 32 + g * 16 + trow;
                LDSM_X4(bH[g], st + ST_B_H + swz(r, c0));
                LDSM_X4(bL[g], st + ST_B_L + swz(r, c0));
            }
            #pragma unroll
            for (int mt = 0; mt < 4; mt++)
                #pragma unroll
                for (int nt = 0; nt < 4; nt++) {
                    const int g = nt >> 1, j = nt & 1;
                    MMA_BF16(acc[mt][nt], aH[mt], bH[g][j], bH[g][j + 2]);
                    MMA_BF16(acc[mt][nt], aH[mt], bL[g][j], bL[g][j + 2]);
                    MMA_BF16(acc[mt][nt], aL[mt], bH[g][j], bH[g][j + 2]);
                }
        }
        __syncthreads();
    }

    float* Cz = Cpart + (size_t)blockIdx.z * Mtot * Nc;
    #pragma unroll
    for (int mt = 0; mt < 4; mt++) {
        #pragma unroll
        for (int nt = 0; nt < 4; nt++) {
            const int m = bm0 + wm * 64 + mt * 16 + (lane >> 2);
            const int n = bn0 + wn * 32 + nt * 8 + (lane & 3) * 2;
            #pragma unroll
            for (int half = 0; half < 2; half++) {
                *reinterpret_cast<float2*>(Cz + (size_t)(m + half * 8) * Nc + n) =
                    make_float2(acc[mt][nt][half * 2], acc[mt][nt][half * 2 + 1]);
            }
        }
    }
}

// -------------------- k5: combine conv partials + bias + split + gram -------
__global__ __launch_bounds__(256) void combine_gram_kernel(const float* __restrict__ conv_b)
{
    __shared__ float s32[32];
    const int i = blockIdx.x, t = threadIdx.x;
    const float sc = 1.f / (float)LREG;

    float4 ap = make_float4(0.f, 0.f, 0.f, 0.f), aq = ap, ar = ap;
    #pragma unroll
    for (int z = 0; z < CONV_SPLIT; z++) {
        const float4* Pz = reinterpret_cast<const float4*>(g_Ypart + (size_t)z * MROWS * DIM);
        ap = f4add(ap, Pz[(size_t)(0 * N_IMG + i) * (DIM / 4) + t]);
        aq = f4add(aq, Pz[(size_t)(1 * N_IMG + i) * (DIM / 4) + t]);
        ar = f4add(ar, Pz[(size_t)(2 * N_IMG + i) * (DIM / 4) + t]);
    }
    const float4 b4 = reinterpret_cast<const float4*>(conv_b)[t];
    float4 yp = make_float4(ap.x * sc + b4.x, ap.y * sc + b4.y,
                            ap.z * sc + b4.z, ap.w * sc + b4.w);
    float4 yq = make_float4(aq.x * sc, aq.y * sc, aq.z * sc, aq.w * sc);
    float4 yr = make_float4(ar.x * sc, ar.y * sc, ar.z * sc, ar.w * sc);

    const size_t d0 = (size_t)t * 4;
    split_store4(g_Y_hi, g_Y_lo, (size_t)(0 * N_IMG + i) * DIM + d0, yp);
    split_store4(g_Y_hi, g_Y_lo, (size_t)(1 * N_IMG + i) * DIM + d0, yq);
    split_store4(g_Y_hi, g_Y_lo, (size_t)(2 * N_IMG + i) * DIM + d0, yr);

    float pp = f4dot(yp, yp), qq = f4dot(yq, yq), rr = f4dot(yr, yr);
    float pq = f4dot(yp, yq), pr = f4dot(yp, yr), qr = f4dot(yq, yr);
    pp = blk_sum(pp, s32); qq = blk_sum(qq, s32); rr = blk_sum(rr, s32);
    pq = blk_sum(pq, s32); pr = blk_sum(pr, s32); qr = blk_sum(qr, s32);
    if (t == 0) {
        float* g = &g_gram[i * 6];
        g[0] = pp; g[1] = qq; g[2] = rr; g[3] = pq; g[4] = pr; g[5] = qr;
    }
}

// -------------------- k7: combine Z partials + final sims -------------------
__global__ __launch_bounds__(256) void final_kernel(float* __restrict__ out)
{
    const int i = blockIdx.x, b = threadIdx.x;
    const float2 w = g_w[b];
    float zp = 0.f, zq = 0.f, zr = 0.f;
    #pragma unroll
    for (int s = 0; s < Z_SPLIT; s++) {
        const float* Zs = g_Zpart + (size_t)s * MROWS * N_CAP;
        zp += Zs[(size_t)(0 * N_IMG + i) * N_CAP + b];
        zq += Zs[(size_t)(1 * N_IMG + i) * N_CAP + b];
        zr += Zs[(size_t)(2 * N_IMG + i) * N_CAP + b];
    }
    const float* g = &g_gram[i * 6];
    const float numer = zp - w.x * zq - w.y * zr;
    const float den2 = g[0] + w.x * w.x * g[1] + w.y * w.y * g[2]
                     - 2.f * w.x * g[3] - 2.f * w.y * g[4] + 2.f * w.x * w.y * g[5];
    out[(size_t)i * N_CAP + b] = numer / (sqrtf(fmaxf(den2, 0.f)) + 1e-8f);
}

// -------------------- launch -------------------------------------------------
extern "C" void kernel_launch(void* const* d_in, const int* in_sizes, int n_in,
                              void* d_out, int out_size)
{
    const float* img    = (const float*)d_in[0];
    const float* cap    = (const float*)d_in[1];
    const int*   lens   = (const int*)  d_in[2];
    const float* red_w  = (const float*)d_in[3];
    const float* red_b  = (const float*)d_in[4];
    const float* proj_w = (const float*)d_in[5];
    const float* proj_b = (const float*)d_in[6];
    const float* conv_w = (const float*)d_in[7];
    const float* conv_b = (const float*)d_in[8];
    float* out = (float*)d_out;

    __nv_bfloat16 *pCVh, *pCVl, *pXh, *pXl, *pWh, *pWl, *pYh, *pYl;
    float *pYp, *pZp;
    cudaGetSymbolAddress((void**)&pCVh, g_cv_hi);
    cudaGetSymbolAddress((void**)&pCVl, g_cv_lo);
    cudaGetSymbolAddress((void**)&pXh,  g_X_hi);
    cudaGetSymbolAddress((void**)&pXl,  g_X_lo);
    cudaGetSymbolAddress((void**)&pWh,  g_W_hi);
    cudaGetSymbolAddress((void**)&pWl,  g_W_lo);
    cudaGetSymbolAddress((void**)&pYh,  g_Y_hi);
    cudaGetSymbolAddress((void**)&pYl,  g_Y_lo);
    cudaGetSymbolAddress((void**)&pYp,  g_Ypart);
    cudaGetSymbolAddress((void**)&pZp,  g_Zpart);

    cudaFuncSetAttribute(hmma_gemm, cudaFuncAttributeMaxDynamicSharedMemorySize, GEMM_SMEM);

    // 1. producers: qprep + wsplit + img_reduce (one launch)
    producers_kernel<<<4 + 256 + 256, 256>>>(img, red_w, red_b, proj_w, proj_b, conv_w);

    // 2. conv GEMM: Ypart[z] = X @ conv_w^T (partial over K), split-K=4
    hmma_gemm<<<dim3(DIM / CTN, MROWS / CTM, CONV_SPLIT), 256, GEMM_SMEM>>>(
        pXh, pXl, pWh, pWl, pYp, DIM, MROWS, DIM, DIM / CONV_SPLIT);

    // 3. caption branch (needs qprep only)
    cap_fused_kernel<<<N_CAP, 1024>>>(cap, lens);

    // 4. combine conv partials, bias+scale, bf16 split of Y, fused Gram
    combine_gram_kernel<<<N_IMG, 256>>>(conv_b);

    // 5. Z GEMM: Zpart[z] = Y @ cap_v^T (partial over K), split-K=16
    hmma_gemm<<<dim3(N_CAP / CTN, MROWS / CTM, Z_SPLIT), 256, GEMM_SMEM>>>(
        pYh, pYl, pCVh, pCVl, pZp, N_CAP, MROWS, DIM, DIM / Z_SPLIT);

    // 6. combine Z partials + final sims
    final_kernel<<<N_IMG, 256>>>(out);
}